// round 10
// baseline (speedup 1.0000x reference)
#include <cuda_runtime.h>
#include <cuda_bf16.h>

// gene_seq (N=256, M=2000) int32 in [0,4); embedding_mat (M=2000, 4, D=128) f32.
// out[n, m, :] = embedding_mat[m, gene_seq[n,m], :] / max(||row||, 1e-12)
//
// R7 shape (best): MTILE=8, 256-thread blocks, grid (250,4)=1000 blocks.
// Register-resident candidate rows per warp, warp-reduced norms, pre-scaled.
// Store policy probe: st.global.wt (write-through) instead of .cs — output
// is 2x L2 capacity and write-once; wt avoids dirty-line allocation/churn
// entirely during graph replay.

#define NM 256
#define MM 2000
#define DD 128
#define MTILE 8
#define NTILE 64
#define THREADS 256
#define ROW_F4 (DD / 4)   // 32 float4 per row

__device__ __forceinline__ float4 sel4(int g, const float4& r0, const float4& r1,
                                       const float4& r2, const float4& r3) {
    int hi = g >> 1, lo = g & 1;
    float4 ta, tb, v;
    ta.x = lo ? r1.x : r0.x;  tb.x = lo ? r3.x : r2.x;  v.x = hi ? tb.x : ta.x;
    ta.y = lo ? r1.y : r0.y;  tb.y = lo ? r3.y : r2.y;  v.y = hi ? tb.y : ta.y;
    ta.z = lo ? r1.z : r0.z;  tb.z = lo ? r3.z : r2.z;  v.z = hi ? tb.z : ta.z;
    ta.w = lo ? r1.w : r0.w;  tb.w = lo ? r3.w : r2.w;  v.w = hi ? tb.w : ta.w;
    return v;
}

__device__ __forceinline__ void stwt4(float4* p, float4 v) {
    asm volatile("st.global.wt.v4.f32 [%0], {%1, %2, %3, %4};"
                 :: "l"(p), "f"(v.x), "f"(v.y), "f"(v.z), "f"(v.w) : "memory");
}

__global__ void __launch_bounds__(THREADS) embed_kernel(
    const int* __restrict__ seq,
    const float* __restrict__ emb,
    float* __restrict__ out)
{
    __shared__ int sseq[NTILE][MTILE];   // 2 KB

    const int m0   = blockIdx.x * MTILE;
    const int n0   = blockIdx.y * NTILE;
    const int tid  = threadIdx.x;
    const int warp = tid >> 5;
    const int lane = tid & 31;
    const int m    = m0 + warp;

    // --- stage seq tile: seq[n0+j][m0+mm], 64x8 ints ---
    #pragma unroll
    for (int i = 0; i < (NTILE * MTILE) / THREADS; i++) {
        int t  = tid + i * THREADS;
        int j  = t >> 3;
        int mm = t & 7;
        sseq[j][mm] = __ldg(seq + (size_t)(n0 + j) * MM + m0 + mm);
    }

    // --- load this warp's 4 candidate rows into registers, normalize ---
    const float4* src = reinterpret_cast<const float4*>(emb + (size_t)m * 4 * DD);
    float4 r0 = __ldg(src + 0 * ROW_F4 + lane);
    float4 r1 = __ldg(src + 1 * ROW_F4 + lane);
    float4 r2 = __ldg(src + 2 * ROW_F4 + lane);
    float4 r3 = __ldg(src + 3 * ROW_F4 + lane);

    float s0 = r0.x*r0.x + r0.y*r0.y + r0.z*r0.z + r0.w*r0.w;
    float s1 = r1.x*r1.x + r1.y*r1.y + r1.z*r1.z + r1.w*r1.w;
    float s2 = r2.x*r2.x + r2.y*r2.y + r2.z*r2.z + r2.w*r2.w;
    float s3 = r3.x*r3.x + r3.y*r3.y + r3.z*r3.z + r3.w*r3.w;
    #pragma unroll
    for (int off = 16; off > 0; off >>= 1) {
        s0 += __shfl_xor_sync(0xFFFFFFFFu, s0, off);
        s1 += __shfl_xor_sync(0xFFFFFFFFu, s1, off);
        s2 += __shfl_xor_sync(0xFFFFFFFFu, s2, off);
        s3 += __shfl_xor_sync(0xFFFFFFFFu, s3, off);
    }
    float c0 = 1.0f / fmaxf(sqrtf(s0), 1e-12f);
    float c1 = 1.0f / fmaxf(sqrtf(s1), 1e-12f);
    float c2 = 1.0f / fmaxf(sqrtf(s2), 1e-12f);
    float c3 = 1.0f / fmaxf(sqrtf(s3), 1e-12f);
    r0.x *= c0; r0.y *= c0; r0.z *= c0; r0.w *= c0;
    r1.x *= c1; r1.y *= c1; r1.z *= c1; r1.w *= c1;
    r2.x *= c2; r2.y *= c2; r2.z *= c2; r2.w *= c2;
    r3.x *= c3; r3.y *= c3; r3.z *= c3; r3.w *= c3;

    __syncthreads();   // sseq ready

    // --- stream outputs: 64 n's, 4 independent write-through stores/iter ---
    float4* dst = reinterpret_cast<float4*>(out + ((size_t)n0 * MM + m) * DD) + lane;
    const size_t nstride = (size_t)MM * ROW_F4;   // float4 stride between n's

    #pragma unroll 4
    for (int j = 0; j < NTILE / 4; j++) {
        int ga = sseq[j][warp];
        int gb = sseq[j + 16][warp];
        int gc = sseq[j + 32][warp];
        int gd = sseq[j + 48][warp];
        float4 va = sel4(ga, r0, r1, r2, r3);
        float4 vb = sel4(gb, r0, r1, r2, r3);
        float4 vc = sel4(gc, r0, r1, r2, r3);
        float4 vd = sel4(gd, r0, r1, r2, r3);
        stwt4(dst + (size_t)(j     ) * nstride, va);
        stwt4(dst + (size_t)(j + 16) * nstride, vb);
        stwt4(dst + (size_t)(j + 32) * nstride, vc);
        stwt4(dst + (size_t)(j + 48) * nstride, vd);
    }
}

extern "C" void kernel_launch(void* const* d_in, const int* in_sizes, int n_in,
                              void* d_out, int out_size) {
    const int*   seq = (const int*)d_in[0];     // (256, 2000) int32
    const float* emb = (const float*)d_in[1];   // (2000, 4, 128) f32
    float*       out = (float*)d_out;           // (256, 2000, 128) f32

    dim3 grid(MM / MTILE, NM / NTILE);          // (250, 4)
    embed_kernel<<<grid, THREADS>>>(seq, emb, out);
}

// round 11
// speedup vs baseline: 1.0951x; 1.0951x over previous
#include <cuda_runtime.h>
#include <cuda_bf16.h>

// gene_seq (N=256, M=2000) int32 in [0,4); embedding_mat (M=2000, 4, D=128) f32.
// out[n, m, :] = embedding_mat[m, gene_seq[n,m], :] / max(||row||, 1e-12)
//
// Converged shape: MTILE=8, 256-thread blocks, grid (250,4)=1000 blocks
// (single wave). Register-resident candidate rows per warp, warp-reduced
// norms, pre-scaled registers. Evict-first (.cs) STG.128 stream — best
// measured store policy (.wb 49.2us / .wt 47.2us / .cs 43.7us).
// This round: 4 independent select+store chains per iteration (was 2).

#define NM 256
#define MM 2000
#define DD 128
#define MTILE 8
#define NTILE 64
#define THREADS 256
#define ROW_F4 (DD / 4)   // 32 float4 per row

__device__ __forceinline__ float4 sel4(int g, const float4& r0, const float4& r1,
                                       const float4& r2, const float4& r3) {
    int hi = g >> 1, lo = g & 1;
    float4 ta, tb, v;
    ta.x = lo ? r1.x : r0.x;  tb.x = lo ? r3.x : r2.x;  v.x = hi ? tb.x : ta.x;
    ta.y = lo ? r1.y : r0.y;  tb.y = lo ? r3.y : r2.y;  v.y = hi ? tb.y : ta.y;
    ta.z = lo ? r1.z : r0.z;  tb.z = lo ? r3.z : r2.z;  v.z = hi ? tb.z : ta.z;
    ta.w = lo ? r1.w : r0.w;  tb.w = lo ? r3.w : r2.w;  v.w = hi ? tb.w : ta.w;
    return v;
}

__global__ void __launch_bounds__(THREADS) embed_kernel(
    const int* __restrict__ seq,
    const float* __restrict__ emb,
    float* __restrict__ out)
{
    __shared__ int sseq[NTILE][MTILE];   // 2 KB

    const int m0   = blockIdx.x * MTILE;
    const int n0   = blockIdx.y * NTILE;
    const int tid  = threadIdx.x;
    const int warp = tid >> 5;
    const int lane = tid & 31;
    const int m    = m0 + warp;

    // --- stage seq tile: seq[n0+j][m0+mm], 64x8 ints ---
    #pragma unroll
    for (int i = 0; i < (NTILE * MTILE) / THREADS; i++) {
        int t  = tid + i * THREADS;
        int j  = t >> 3;
        int mm = t & 7;
        sseq[j][mm] = __ldg(seq + (size_t)(n0 + j) * MM + m0 + mm);
    }

    // --- load this warp's 4 candidate rows into registers, normalize ---
    const float4* src = reinterpret_cast<const float4*>(emb + (size_t)m * 4 * DD);
    float4 r0 = __ldg(src + 0 * ROW_F4 + lane);
    float4 r1 = __ldg(src + 1 * ROW_F4 + lane);
    float4 r2 = __ldg(src + 2 * ROW_F4 + lane);
    float4 r3 = __ldg(src + 3 * ROW_F4 + lane);

    float s0 = r0.x*r0.x + r0.y*r0.y + r0.z*r0.z + r0.w*r0.w;
    float s1 = r1.x*r1.x + r1.y*r1.y + r1.z*r1.z + r1.w*r1.w;
    float s2 = r2.x*r2.x + r2.y*r2.y + r2.z*r2.z + r2.w*r2.w;
    float s3 = r3.x*r3.x + r3.y*r3.y + r3.z*r3.z + r3.w*r3.w;
    #pragma unroll
    for (int off = 16; off > 0; off >>= 1) {
        s0 += __shfl_xor_sync(0xFFFFFFFFu, s0, off);
        s1 += __shfl_xor_sync(0xFFFFFFFFu, s1, off);
        s2 += __shfl_xor_sync(0xFFFFFFFFu, s2, off);
        s3 += __shfl_xor_sync(0xFFFFFFFFu, s3, off);
    }
    float c0 = 1.0f / fmaxf(sqrtf(s0), 1e-12f);
    float c1 = 1.0f / fmaxf(sqrtf(s1), 1e-12f);
    float c2 = 1.0f / fmaxf(sqrtf(s2), 1e-12f);
    float c3 = 1.0f / fmaxf(sqrtf(s3), 1e-12f);
    r0.x *= c0; r0.y *= c0; r0.z *= c0; r0.w *= c0;
    r1.x *= c1; r1.y *= c1; r1.z *= c1; r1.w *= c1;
    r2.x *= c2; r2.y *= c2; r2.z *= c2; r2.w *= c2;
    r3.x *= c3; r3.y *= c3; r3.z *= c3; r3.w *= c3;

    __syncthreads();   // sseq ready

    // --- stream outputs: 64 n's, 4 independent select+store chains/iter ---
    float4* dst = reinterpret_cast<float4*>(out + ((size_t)n0 * MM + m) * DD) + lane;
    const size_t nstride = (size_t)MM * ROW_F4;   // float4 stride between n's

    #pragma unroll 4
    for (int j = 0; j < NTILE / 4; j++) {
        int ga = sseq[j][warp];
        int gb = sseq[j + 16][warp];
        int gc = sseq[j + 32][warp];
        int gd = sseq[j + 48][warp];
        float4 va = sel4(ga, r0, r1, r2, r3);
        float4 vb = sel4(gb, r0, r1, r2, r3);
        float4 vc = sel4(gc, r0, r1, r2, r3);
        float4 vd = sel4(gd, r0, r1, r2, r3);
        __stcs(dst + (size_t)(j     ) * nstride, va);   // STG.E.128 evict-first
        __stcs(dst + (size_t)(j + 16) * nstride, vb);
        __stcs(dst + (size_t)(j + 32) * nstride, vc);
        __stcs(dst + (size_t)(j + 48) * nstride, vd);
    }
}

extern "C" void kernel_launch(void* const* d_in, const int* in_sizes, int n_in,
                              void* d_out, int out_size) {
    const int*   seq = (const int*)d_in[0];     // (256, 2000) int32
    const float* emb = (const float*)d_in[1];   // (2000, 4, 128) f32
    float*       out = (float*)d_out;           // (256, 2000, 128) f32

    dim3 grid(MM / MTILE, NM / NTILE);          // (250, 4)
    embed_kernel<<<grid, THREADS>>>(seq, emb, out);
}